// round 15
// baseline (speedup 1.0000x reference)
#include <cuda_runtime.h>
#include <cuda_fp16.h>
#include <cstdint>
#include <cstddef>

#define LSEQ 512
#define NBATCH 512
#define IDIM 128
#define HDIM 128
#define GDIM 512   // 4*H

// Scratch: packed fp16 pre-activation input gates.
// Layout: [m = t*N+n][hcol 0..127][gate 0..3]  -> 8 bytes per (m, hcol)
// Padded by 1 step so the t+1 prefetch needs no bounds check.
__device__ __half g_XgH[(size_t)(LSEQ + 1) * NBATCH * GDIM];

// ---------------------------------------------------------------------------
// helpers
// ---------------------------------------------------------------------------
__device__ __forceinline__ uint32_t f2h2(float a, float b) {
    __half2 h = __floats2half2_rn(a, b);
    return *reinterpret_cast<uint32_t*>(&h);
}

__device__ __forceinline__ void mma16816(float* d,
    uint32_t a0, uint32_t a1, uint32_t a2, uint32_t a3,
    uint32_t b0, uint32_t b1)
{
    asm volatile(
        "mma.sync.aligned.m16n8k16.row.col.f32.f16.f16.f32 "
        "{%0,%1,%2,%3}, {%4,%5,%6,%7}, {%8,%9}, {%0,%1,%2,%3};\n"
        : "+f"(d[0]), "+f"(d[1]), "+f"(d[2]), "+f"(d[3])
        : "r"(a0), "r"(a1), "r"(a2), "r"(a3), "r"(b0), "r"(b1));
}

__device__ __forceinline__ void ldsm4(uint32_t& a0, uint32_t& a1,
                                      uint32_t& a2, uint32_t& a3, uint32_t saddr)
{
    asm volatile("ldmatrix.sync.aligned.m8n8.x4.shared.b16 {%0,%1,%2,%3}, [%4];"
                 : "=r"(a0), "=r"(a1), "=r"(a2), "=r"(a3) : "r"(saddr));
}

// hardware tanh (MUFU.TANH): 1 MUFU op
__device__ __forceinline__ float tanhg(float x) {
    float y; asm("tanh.approx.f32 %0, %1;" : "=f"(y) : "f"(x)); return y;
}
// sigmoid via tanh identity: 1 MUFU + 1 FMA
__device__ __forceinline__ float sigg(float x) {
    return __fmaf_rn(0.5f, tanhg(0.5f * x), 0.5f);
}

// ---------------------------------------------------------------------------
// Phase 1: Xg = x@W_ih^T + (b_ih+b_hh), packed fp16 [m][hcol][gate].
// Occupancy-2 version (R14, proven): 256 threads/block, 2 CTAs/SM, block-pair
// splits hcols. Grid 2048.
// ---------------------------------------------------------------------------
__global__ void __launch_bounds__(256, 2)
pregemm_kernel(const float* __restrict__ x,
               const float* __restrict__ Wih,
               const float* __restrict__ bih,
               const float* __restrict__ bhh)
{
    __shared__ __half Ash[2][32][136];

    const int tid  = threadIdx.x;
    const int warp = tid >> 5;
    const int lane = tid & 31;
    const int q    = lane & 3;
    const int r0   = lane >> 2;
    const int chalf = blockIdx.x & 1;
    const size_t m_base = (size_t)(blockIdx.x >> 1) * 256;
    const int c0 = chalf * 64 + warp * 8 + q * 2;

    uint32_t bfrag[4][8][2];
#pragma unroll
    for (int j = 0; j < 4; j++) {
        const float* wr = Wih + (size_t)(j * 128 + chalf * 64 + warp * 8 + r0) * IDIM;
#pragma unroll
        for (int kt = 0; kt < 8; kt++) {
            const int k = kt * 16 + q * 2;
            float2 w0 = *reinterpret_cast<const float2*>(wr + k);
            float2 w1 = *reinterpret_cast<const float2*>(wr + k + 8);
            bfrag[j][kt][0] = f2h2(w0.x, w0.y);
            bfrag[j][kt][1] = f2h2(w1.x, w1.y);
        }
    }

    float bx[4], by[4];
#pragma unroll
    for (int j = 0; j < 4; j++) {
        bx[j] = bih[j * 128 + c0]     + bhh[j * 128 + c0];
        by[j] = bih[j * 128 + c0 + 1] + bhh[j * 128 + c0 + 1];
    }

    const int lr = tid >> 3;
    const int lc = (tid & 7) * 16;
    const int lm_row = lane & 15;
    const int lm_col = (lane >> 4) * 8;

    float4 v0 = *reinterpret_cast<const float4*>(x + (m_base + lr) * IDIM + lc);
    float4 v1 = *reinterpret_cast<const float4*>(x + (m_base + lr) * IDIM + lc + 4);
    float4 v2 = *reinterpret_cast<const float4*>(x + (m_base + lr) * IDIM + lc + 8);
    float4 v3 = *reinterpret_cast<const float4*>(x + (m_base + lr) * IDIM + lc + 12);

#pragma unroll 1
    for (int s = 0; s < 8; s++) {
        const int buf = s & 1;
        {
            __half2* sp = reinterpret_cast<__half2*>(&Ash[buf][lr][lc]);
            sp[0] = __floats2half2_rn(v0.x, v0.y);
            sp[1] = __floats2half2_rn(v0.z, v0.w);
            sp[2] = __floats2half2_rn(v1.x, v1.y);
            sp[3] = __floats2half2_rn(v1.z, v1.w);
            sp[4] = __floats2half2_rn(v2.x, v2.y);
            sp[5] = __floats2half2_rn(v2.z, v2.w);
            sp[6] = __floats2half2_rn(v3.x, v3.y);
            sp[7] = __floats2half2_rn(v3.z, v3.w);
        }
        __syncthreads();

        if (s < 7) {
            const size_t mr = m_base + (s + 1) * 32 + lr;
            v0 = *reinterpret_cast<const float4*>(x + mr * IDIM + lc);
            v1 = *reinterpret_cast<const float4*>(x + mr * IDIM + lc + 4);
            v2 = *reinterpret_cast<const float4*>(x + mr * IDIM + lc + 8);
            v3 = *reinterpret_cast<const float4*>(x + mr * IDIM + lc + 12);
        }

        float acc[2][4][4];
#pragma unroll
        for (int mi = 0; mi < 2; mi++)
#pragma unroll
            for (int j = 0; j < 4; j++)
#pragma unroll
                for (int p = 0; p < 4; p++) acc[mi][j][p] = 0.0f;

#pragma unroll
        for (int kt = 0; kt < 8; kt++) {
#pragma unroll
            for (int mi = 0; mi < 2; mi++) {
                uint32_t a0, a1, a2, a3;
                uint32_t saddr = (uint32_t)__cvta_generic_to_shared(
                    &Ash[buf][mi * 16 + lm_row][kt * 16 + lm_col]);
                ldsm4(a0, a1, a2, a3, saddr);
#pragma unroll
                for (int j = 0; j < 4; j++)
                    mma16816(acc[mi][j], a0, a1, a2, a3, bfrag[j][kt][0], bfrag[j][kt][1]);
            }
        }

        const size_t m0 = m_base + s * 32;
#pragma unroll
        for (int mi = 0; mi < 2; mi++) {
#pragma unroll
            for (int half_ = 0; half_ < 2; half_++) {
                const size_t row = m0 + mi * 16 + r0 + half_ * 8;
                const int pa = half_ * 2;
                uint4 v;
                v.x = f2h2(acc[mi][0][pa]     + bx[0], acc[mi][1][pa]     + bx[1]);
                v.y = f2h2(acc[mi][2][pa]     + bx[2], acc[mi][3][pa]     + bx[3]);
                v.z = f2h2(acc[mi][0][pa + 1] + by[0], acc[mi][1][pa + 1] + by[1]);
                v.w = f2h2(acc[mi][2][pa + 1] + by[2], acc[mi][3][pa + 1] + by[3]);
                *reinterpret_cast<uint4*>(&g_XgH[(row * 128 + c0) * 4]) = v;
            }
        }
    }
}

// ---------------------------------------------------------------------------
// Phase 2: masked LSTM recurrence — TWO INTERLEAVED CHAINS per block.
// Each block owns 8 batch rows: chain A = rows n0..n0+3, chain B = n0+4..n0+7,
// sharing the same W_hh A-fragments (registers). Pipeline per iteration:
//   epi_B(t-1) | bar | MMA_B(t) issue | epi_A(t) | bar | MMA_A(t+1) issue
// so every chain's MUFU/L1 epilogue executes under the tensor pipe running
// the OTHER chain's MMAs; acc results are consumed two phases after issue.
// Single-buffered h per chain (write/read separated by a barrier each way).
// R12's proven core per chain: pre-fragmented B, gate-interleaved tiles,
// in-register gate epilogue. Grid 64 blocks x 8 rows, 512 threads.
// ---------------------------------------------------------------------------
__global__ void __launch_bounds__(512, 1)
lstm_rec_kernel(const float* __restrict__ hc,
                const int*   __restrict__ is_init,
                const float* __restrict__ Whh,
                float* __restrict__ out)
{
    __shared__ uint4 bbufA[4][16];        // chain A h fragments (1KB)
    __shared__ uint4 bbufB[4][16];        // chain B h fragments (1KB)
    __shared__ float msk[LSEQ][8];        // mask table (16KB)

    const int tid  = threadIdx.x;
    const int warp = tid >> 5;
    const int lane = tid & 31;
    const int q    = lane & 3;
    const int r0   = lane >> 2;
    const int n0   = blockIdx.x * 8;

    // in-register element ownership: lane (r0,q) -> (col, nsel)
    const int col  = warp * 8 + r0;             // global hcol
    const int nsel = 2 * (q & 1) + (q >> 1);    // row-in-chain 0..3
    const int hi   = q >> 1;                    // accumulator parity
    const int nA   = n0 + nsel;
    const int nB   = n0 + 4 + nsel;

    // fragment-slot byte offset for this lane's h element (R12 layout):
    const int fkt  = col >> 4;
    const int fr   = col & 15;
    const int fl16 = nsel * 4 + ((fr & 7) >> 1);
    const uint32_t fragOff = (uint32_t)((((fkt >> 1) * 16 + fl16) * 16) +
                                        (fkt & 1) * 8 +
                                        ((fr & 8) ? 4 : 0) + (col & 1) * 2);
    const uint32_t baseA = (uint32_t)__cvta_generic_to_shared(&bbufA[0][0]);
    const uint32_t baseB = (uint32_t)__cvta_generic_to_shared(&bbufB[0][0]);

    // --- A-fragments (gate-interleaved tiles), loaded once, SHARED by chains ---
    uint32_t afrag[2][8][4];
#pragma unroll
    for (int mt = 0; mt < 2; mt++) {
        const float* wlo = Whh + (size_t)((2 * mt)     * 128 + warp * 8 + r0) * HDIM;
        const float* whi = Whh + (size_t)((2 * mt + 1) * 128 + warp * 8 + r0) * HDIM;
#pragma unroll
        for (int kt = 0; kt < 8; kt++) {
            const int k = kt * 16 + q * 2;
            float2 w00 = *reinterpret_cast<const float2*>(wlo + k);
            float2 w01 = *reinterpret_cast<const float2*>(wlo + k + 8);
            float2 w10 = *reinterpret_cast<const float2*>(whi + k);
            float2 w11 = *reinterpret_cast<const float2*>(whi + k + 8);
            afrag[mt][kt][0] = f2h2(w00.x, w00.y);
            afrag[mt][kt][1] = f2h2(w10.x, w10.y);
            afrag[mt][kt][2] = f2h2(w01.x, w01.y);
            afrag[mt][kt][3] = f2h2(w11.x, w11.y);
        }
    }

    // --- mask table (8 rows per block) ---
    for (int idx = tid; idx < LSEQ * 8; idx += 512) {
        const int t = idx >> 3, r = idx & 7;
        msk[t][r] = 1.0f - (float)is_init[(size_t)t * NBATCH + n0 + r];
    }
    __syncthreads();

    // --- init both chains (t=0 mask applied) ---
    const float m0A = msk[0][nsel];
    const float m0B = msk[0][4 + nsel];
    float cregA = hc[(size_t)nA * 256 + 128 + col] * m0A;
    float cregB = hc[(size_t)nB * 256 + 128 + col] * m0B;
    {
        const __half hA0 = __float2half(hc[(size_t)nA * 256 + col] * m0A);
        const __half hB0 = __float2half(hc[(size_t)nB * 256 + col] * m0B);
        asm volatile("st.shared.u16 [%0], %1;"
                     :: "r"(baseA + fragOff), "h"(*reinterpret_cast<const uint16_t*>(&hA0)));
        asm volatile("st.shared.u16 [%0], %1;"
                     :: "r"(baseB + fragOff), "h"(*reinterpret_cast<const uint16_t*>(&hB0)));
    }
    __syncthreads();   // h_A(0), h_B(0) visible

    const uint2* xgp = reinterpret_cast<const uint2*>(g_XgH);
    uint2 xA     = __ldg(&xgp[(size_t)nA * 128 + col]);   // Xg_A(0)
    uint2 xB     = __ldg(&xgp[(size_t)nB * 128 + col]);   // Xg_B(t)
    uint2 xBprev = xB;                                    // Xg_B(t-1)

    const uint32_t bReadA = baseA + (uint32_t)(lane & 15) * 16;
    const uint32_t bReadB = baseB + (uint32_t)(lane & 15) * 16;

    const size_t OUT_HC = (size_t)LSEQ * NBATCH * HDIM;

    float accA[2][4], accB[2][4];

    // --- issue MMA_A(0) ---
#pragma unroll
    for (int mt = 0; mt < 2; mt++)
#pragma unroll
        for (int p = 0; p < 4; p++) accA[mt][p] = 0.0f;
#pragma unroll
    for (int kt2 = 0; kt2 < 4; kt2++) {
        uint32_t b0, b1, c0_, c1_;
        asm volatile("ld.shared.v4.u32 {%0,%1,%2,%3}, [%4];"
                     : "=r"(b0), "=r"(b1), "=r"(c0_), "=r"(c1_)
                     : "r"(bReadA + kt2 * 256));
#pragma unroll
        for (int mt = 0; mt < 2; mt++) {
            mma16816(accA[mt], afrag[mt][2*kt2][0],   afrag[mt][2*kt2][1],
                               afrag[mt][2*kt2][2],   afrag[mt][2*kt2][3],   b0, b1);
            mma16816(accA[mt], afrag[mt][2*kt2+1][0], afrag[mt][2*kt2+1][1],
                               afrag[mt][2*kt2+1][2], afrag[mt][2*kt2+1][3], c0_, c1_);
        }
    }

#pragma unroll 1
    for (int t = 0; t < LSEQ; t++) {
        // state-independent prefetches (t+1; array padded)
        uint2 xnA = __ldg(&xgp[((size_t)(t + 1) * NBATCH + nA) * 128 + col]);
        uint2 xnB = __ldg(&xgp[((size_t)(t + 1) * NBATCH + nB) * 128 + col]);

        // --- epi_B(t-1): consume accB (MMA_B(t-1)), publish h_B(t) ---
        if (t) {
            const float gi = hi ? accB[0][1] : accB[0][0];
            const float gf = hi ? accB[0][3] : accB[0][2];
            const float gg = hi ? accB[1][1] : accB[1][0];
            const float go = hi ? accB[1][3] : accB[1][2];
            const float2 x01 = __half22float2(*reinterpret_cast<__half2*>(&xBprev.x));
            const float2 x23 = __half22float2(*reinterpret_cast<__half2*>(&xBprev.y));
            const float i_ = sigg(gi + x01.x);
            const float f_ = sigg(gf + x01.y);
            const float g_ = tanhg(gg + x23.x);
            const float o_ = sigg(go + x23.y);
            const float cn = __fmaf_rn(f_, cregB, i_ * g_);
            const float hv = o_ * tanhg(cn);
            const float mn = msk[t][4 + nsel];      // mask entering step t
            cregB = cn * mn;
            const __half hm = __float2half(hv * mn);
            asm volatile("st.shared.u16 [%0], %1;"
                         :: "r"(baseB + fragOff), "h"(*reinterpret_cast<const uint16_t*>(&hm)));
            out[((size_t)(t - 1) * NBATCH + nB) * HDIM + col] = hv;
        }
        __syncthreads();   // bar1: h_B(t) visible; all LDS_A(t) long done

        // --- issue MMA_B(t) ---
#pragma unroll
        for (int mt = 0; mt < 2; mt++)
#pragma unroll
            for (int p = 0; p < 4; p++) accB[mt][p] = 0.0f;
#pragma unroll
        for (int kt2 = 0; kt2 < 4; kt2++) {
            uint32_t b0, b1, c0_, c1_;
            asm volatile("ld.shared.v4.u32 {%0,%1,%2,%3}, [%4];"
                         : "=r"(b0), "=r"(b1), "=r"(c0_), "=r"(c1_)
                         : "r"(bReadB + kt2 * 256));
#pragma unroll
            for (int mt = 0; mt < 2; mt++) {
                mma16816(accB[mt], afrag[mt][2*kt2][0],   afrag[mt][2*kt2][1],
                                   afrag[mt][2*kt2][2],   afrag[mt][2*kt2][3],   b0, b1);
                mma16816(accB[mt], afrag[mt][2*kt2+1][0], afrag[mt][2*kt2+1][1],
                                   afrag[mt][2*kt2+1][2], afrag[mt][2*kt2+1][3], c0_, c1_);
            }
        }

        // --- epi_A(t): consume accA (MMA_A(t)), publish h_A(t+1) ---
        {
            const float gi = hi ? accA[0][1] : accA[0][0];
            const float gf = hi ? accA[0][3] : accA[0][2];
            const float gg = hi ? accA[1][1] : accA[1][0];
            const float go = hi ? accA[1][3] : accA[1][2];
            const float2 x01 = __half22float2(*reinterpret_cast<__half2*>(&xA.x));
            const float2 x23 = __half22float2(*reinterpret_cast<__half2*>(&xA.y));
            const float i_ = sigg(gi + x01.x);
            const float f_ = sigg(gf + x01.y);
            const float g_ = tanhg(gg + x23.x);
            const float o_ = sigg(go + x23.y);
            const float cn = __fmaf_rn(f_, cregA, i_ * g_);
            const float hv = o_ * tanhg(cn);
            const float mn = (t < LSEQ - 1) ? msk[t + 1][nsel] : 1.0f;
            cregA = cn * mn;
            const __half hm = __float2half(hv * mn);
            asm volatile("st.shared.u16 [%0], %1;"
                         :: "r"(baseA + fragOff), "h"(*reinterpret_cast<const uint16_t*>(&hm)));
            out[((size_t)t * NBATCH + nA) * HDIM + col] = hv;
            if (t == LSEQ - 1) {
                out[OUT_HC + (size_t)nA * 256 + col]       = hv;
                out[OUT_HC + (size_t)nA * 256 + 128 + col] = cn;
            }
        }
        __syncthreads();   // bar2: h_A(t+1) visible; all LDS_B(t) done

        // --- issue MMA_A(t+1) ---
        if (t < LSEQ - 1) {
#pragma unroll
            for (int mt = 0; mt < 2; mt++)
#pragma unroll
                for (int p = 0; p < 4; p++) accA[mt][p] = 0.0f;
#pragma unroll
            for (int kt2 = 0; kt2 < 4; kt2++) {
                uint32_t b0, b1, c0_, c1_;
                asm volatile("ld.shared.v4.u32 {%0,%1,%2,%3}, [%4];"
                             : "=r"(b0), "=r"(b1), "=r"(c0_), "=r"(c1_)
                             : "r"(bReadA + kt2 * 256));
#pragma unroll
                for (int mt = 0; mt < 2; mt++) {
                    mma16816(accA[mt], afrag[mt][2*kt2][0],   afrag[mt][2*kt2][1],
                                       afrag[mt][2*kt2][2],   afrag[mt][2*kt2][3],   b0, b1);
                    mma16816(accA[mt], afrag[mt][2*kt2+1][0], afrag[mt][2*kt2+1][1],
                                       afrag[mt][2*kt2+1][2], afrag[mt][2*kt2+1][3], c0_, c1_);
                }
            }
        }

        xBprev = xB; xB = xnB; xA = xnA;
    }

    // --- tail: epi_B(511) ---
    {
        const float gi = hi ? accB[0][1] : accB[0][0];
        const float gf = hi ? accB[0][3] : accB[0][2];
        const float gg = hi ? accB[1][1] : accB[1][0];
        const float go = hi ? accB[1][3] : accB[1][2];
        const float2 x01 = __half22float2(*reinterpret_cast<__half2*>(&xBprev.x));
        const float2 x23 = __half22float2(*reinterpret_cast<__half2*>(&xBprev.y));
        const float i_ = sigg(gi + x01.x);
        const float f_ = sigg(gf + x01.y);
        const float g_ = tanhg(gg + x23.x);
        const float o_ = sigg(go + x23.y);
        const float cn = __fmaf_rn(f_, cregB, i_ * g_);
        const float hv = o_ * tanhg(cn);
        out[((size_t)(LSEQ - 1) * NBATCH + nB) * HDIM + col] = hv;
        out[OUT_HC + (size_t)nB * 256 + col]       = hv;
        out[OUT_HC + (size_t)nB * 256 + 128 + col] = cn;
    }
}

// ---------------------------------------------------------------------------
extern "C" void kernel_launch(void* const* d_in, const int* in_sizes, int n_in,
                              void* d_out, int out_size)
{
    const float* input   = (const float*)d_in[0];  // [L,N,I] fp32
    const float* hc      = (const float*)d_in[1];  // [N,2H]  fp32
    const int*   is_init = (const int*)  d_in[2];  // [L,N]   int32
    const float* Wih     = (const float*)d_in[3];  // [4H,I]
    const float* Whh     = (const float*)d_in[4];  // [4H,H]
    const float* bih     = (const float*)d_in[5];  // [4H]
    const float* bhh     = (const float*)d_in[6];  // [4H]
    float* out = (float*)d_out;                    // [L,N,H] then [N,2H]

    pregemm_kernel<<<(LSEQ * NBATCH / 256) * 2, 256>>>(input, Wih, bih, bhh);
    lstm_rec_kernel<<<NBATCH / 8, 512>>>(hc, is_init, Whh, out);
}

// round 16
// speedup vs baseline: 1.7605x; 1.7605x over previous
#include <cuda_runtime.h>
#include <cuda_fp16.h>
#include <cstdint>
#include <cstddef>

#define LSEQ 512
#define NBATCH 512
#define IDIM 128
#define HDIM 128
#define GDIM 512   // 4*H

// Scratch: packed fp16 pre-activation input gates.
// Layout: [m = t*N+n][hcol 0..127][gate 0..3]  -> 8 bytes per (m, hcol)
// Padded by 1 step so the t+1 prefetch needs no bounds check.
__device__ __half g_XgH[(size_t)(LSEQ + 1) * NBATCH * GDIM];

// ---------------------------------------------------------------------------
// helpers
// ---------------------------------------------------------------------------
__device__ __forceinline__ uint32_t f2h2(float a, float b) {
    __half2 h = __floats2half2_rn(a, b);
    return *reinterpret_cast<uint32_t*>(&h);
}

__device__ __forceinline__ void mma16816(float* d,
    uint32_t a0, uint32_t a1, uint32_t a2, uint32_t a3,
    uint32_t b0, uint32_t b1)
{
    asm volatile(
        "mma.sync.aligned.m16n8k16.row.col.f32.f16.f16.f32 "
        "{%0,%1,%2,%3}, {%4,%5,%6,%7}, {%8,%9}, {%0,%1,%2,%3};\n"
        : "+f"(d[0]), "+f"(d[1]), "+f"(d[2]), "+f"(d[3])
        : "r"(a0), "r"(a1), "r"(a2), "r"(a3), "r"(b0), "r"(b1));
}

__device__ __forceinline__ void ldsm4(uint32_t& a0, uint32_t& a1,
                                      uint32_t& a2, uint32_t& a3, uint32_t saddr)
{
    asm volatile("ldmatrix.sync.aligned.m8n8.x4.shared.b16 {%0,%1,%2,%3}, [%4];"
                 : "=r"(a0), "=r"(a1), "=r"(a2), "=r"(a3) : "r"(saddr));
}

// hardware tanh (MUFU.TANH): 1 MUFU op
__device__ __forceinline__ float tanhg(float x) {
    float y; asm("tanh.approx.f32 %0, %1;" : "=f"(y) : "f"(x)); return y;
}
// sigmoid via tanh identity: 1 MUFU + 1 FMA
__device__ __forceinline__ float sigg(float x) {
    return __fmaf_rn(0.5f, tanhg(0.5f * x), 0.5f);
}

// half-K handoff barriers: 256 arrivers (8 warps) + 512 syncers = 768
__device__ __forceinline__ void nbar_sync768(int id) {
    asm volatile("bar.sync %0, 768;" :: "r"(id) : "memory");
}
__device__ __forceinline__ void nbar_arrive768(int id) {
    asm volatile("bar.arrive %0, 768;" :: "r"(id) : "memory");
}

// ---------------------------------------------------------------------------
// Phase 1: Xg = x@W_ih^T + (b_ih+b_hh), packed fp16 [m][hcol][gate].
// Occupancy-2 version (R14, proven): 256 threads/block, 2 CTAs/SM, block-pair
// splits hcols. Grid 2048.
// ---------------------------------------------------------------------------
__global__ void __launch_bounds__(256, 2)
pregemm_kernel(const float* __restrict__ x,
               const float* __restrict__ Wih,
               const float* __restrict__ bih,
               const float* __restrict__ bhh)
{
    __shared__ __half Ash[2][32][136];

    const int tid  = threadIdx.x;
    const int warp = tid >> 5;
    const int lane = tid & 31;
    const int q    = lane & 3;
    const int r0   = lane >> 2;
    const int chalf = blockIdx.x & 1;
    const size_t m_base = (size_t)(blockIdx.x >> 1) * 256;
    const int c0 = chalf * 64 + warp * 8 + q * 2;

    uint32_t bfrag[4][8][2];
#pragma unroll
    for (int j = 0; j < 4; j++) {
        const float* wr = Wih + (size_t)(j * 128 + chalf * 64 + warp * 8 + r0) * IDIM;
#pragma unroll
        for (int kt = 0; kt < 8; kt++) {
            const int k = kt * 16 + q * 2;
            float2 w0 = *reinterpret_cast<const float2*>(wr + k);
            float2 w1 = *reinterpret_cast<const float2*>(wr + k + 8);
            bfrag[j][kt][0] = f2h2(w0.x, w0.y);
            bfrag[j][kt][1] = f2h2(w1.x, w1.y);
        }
    }

    float bx[4], by[4];
#pragma unroll
    for (int j = 0; j < 4; j++) {
        bx[j] = bih[j * 128 + c0]     + bhh[j * 128 + c0];
        by[j] = bih[j * 128 + c0 + 1] + bhh[j * 128 + c0 + 1];
    }

    const int lr = tid >> 3;
    const int lc = (tid & 7) * 16;
    const int lm_row = lane & 15;
    const int lm_col = (lane >> 4) * 8;

    float4 v0 = *reinterpret_cast<const float4*>(x + (m_base + lr) * IDIM + lc);
    float4 v1 = *reinterpret_cast<const float4*>(x + (m_base + lr) * IDIM + lc + 4);
    float4 v2 = *reinterpret_cast<const float4*>(x + (m_base + lr) * IDIM + lc + 8);
    float4 v3 = *reinterpret_cast<const float4*>(x + (m_base + lr) * IDIM + lc + 12);

#pragma unroll 1
    for (int s = 0; s < 8; s++) {
        const int buf = s & 1;
        {
            __half2* sp = reinterpret_cast<__half2*>(&Ash[buf][lr][lc]);
            sp[0] = __floats2half2_rn(v0.x, v0.y);
            sp[1] = __floats2half2_rn(v0.z, v0.w);
            sp[2] = __floats2half2_rn(v1.x, v1.y);
            sp[3] = __floats2half2_rn(v1.z, v1.w);
            sp[4] = __floats2half2_rn(v2.x, v2.y);
            sp[5] = __floats2half2_rn(v2.z, v2.w);
            sp[6] = __floats2half2_rn(v3.x, v3.y);
            sp[7] = __floats2half2_rn(v3.z, v3.w);
        }
        __syncthreads();

        if (s < 7) {
            const size_t mr = m_base + (s + 1) * 32 + lr;
            v0 = *reinterpret_cast<const float4*>(x + mr * IDIM + lc);
            v1 = *reinterpret_cast<const float4*>(x + mr * IDIM + lc + 4);
            v2 = *reinterpret_cast<const float4*>(x + mr * IDIM + lc + 8);
            v3 = *reinterpret_cast<const float4*>(x + mr * IDIM + lc + 12);
        }

        float acc[2][4][4];
#pragma unroll
        for (int mi = 0; mi < 2; mi++)
#pragma unroll
            for (int j = 0; j < 4; j++)
#pragma unroll
                for (int p = 0; p < 4; p++) acc[mi][j][p] = 0.0f;

#pragma unroll
        for (int kt = 0; kt < 8; kt++) {
#pragma unroll
            for (int mi = 0; mi < 2; mi++) {
                uint32_t a0, a1, a2, a3;
                uint32_t saddr = (uint32_t)__cvta_generic_to_shared(
                    &Ash[buf][mi * 16 + lm_row][kt * 16 + lm_col]);
                ldsm4(a0, a1, a2, a3, saddr);
#pragma unroll
                for (int j = 0; j < 4; j++)
                    mma16816(acc[mi][j], a0, a1, a2, a3, bfrag[j][kt][0], bfrag[j][kt][1]);
            }
        }

        const size_t m0 = m_base + s * 32;
#pragma unroll
        for (int mi = 0; mi < 2; mi++) {
#pragma unroll
            for (int half_ = 0; half_ < 2; half_++) {
                const size_t row = m0 + mi * 16 + r0 + half_ * 8;
                const int pa = half_ * 2;
                uint4 v;
                v.x = f2h2(acc[mi][0][pa]     + bx[0], acc[mi][1][pa]     + bx[1]);
                v.y = f2h2(acc[mi][2][pa]     + bx[2], acc[mi][3][pa]     + bx[3]);
                v.z = f2h2(acc[mi][0][pa + 1] + by[0], acc[mi][1][pa + 1] + by[1]);
                v.w = f2h2(acc[mi][2][pa + 1] + by[2], acc[mi][3][pa + 1] + by[3]);
                *reinterpret_cast<uint4*>(&g_XgH[(row * 128 + c0) * 4]) = v;
            }
        }
    }
}

// ---------------------------------------------------------------------------
// Phase 2: masked LSTM recurrence — MASK-CHUNKED time parallelism.
// is_initial ~ Bern(0.5): a 256-step window contains a reset per row w.p.
// 1-2^-256. Grid = 64 n-groups x 2 time-chunks = 128 blocks x 8 rows.
//   chunk0: t in [0, pmax)   from the true initial state (pmax = max first
//           reset in [256,512) over the block's 8 rows; 512 if none).
//   chunk1: t in [256, 512)  from a ZERO state; write-ahead masking zeroes
//           the state at each row's first reset p_n, so results for t>=p_n
//           are bitwise identical to the sequential run. Stores only t>=p_n.
// Overlap region [p_n, pmax): both chunks write bitwise-identical values.
// Final hc: chunk1 stores rows with p_n<512; chunk0 stores the rest.
// Core per step: R12's transposed W-stationary GEMM + pre-fragmented B with
// ALL 8 n-columns valid (no duplication): each lane owns TWO elements
// (n=2q, 2q+1) fully in-register. 16 MMA/warp/step covers 8 rows.
// Half-K handoff named barriers as in R12.
// ---------------------------------------------------------------------------
__global__ void __launch_bounds__(512, 1)
lstm_rec_kernel(const float* __restrict__ hc,
                const int*   __restrict__ is_init,
                const float* __restrict__ Whh,
                float* __restrict__ out)
{
    __shared__ uint4 bbuf[2][4][32];      // pre-fragmented h, 8 rows (4KB)
    __shared__ float msk[LSEQ][8];        // mask table (16KB)
    __shared__ int   pp[8];               // first reset in [256,512) per row

    const int tid  = threadIdx.x;
    const int warp = tid >> 5;
    const int lane = tid & 31;
    const int q    = lane & 3;
    const int r0   = lane >> 2;
    const int ng   = blockIdx.x >> 1;
    const int chunk = blockIdx.x & 1;
    const int n0   = ng * 8;

    // each lane owns TWO elements: (col, n=2q) and (col, n=2q+1)
    const int col = warp * 8 + r0;
    const int ne0 = 2 * q;
    const int ne1 = 2 * q + 1;
    const int ng0 = n0 + ne0;
    const int ng1 = n0 + ne1;
    const int myHalf = warp >> 3;

    // fragment-slot byte offset (within one buf) for element (n, col):
    // bbuf[buf][kt2][slot] 16B: slot = n*4 + ((col&7)>>1); +8 if kt odd;
    // +4 if (col&8); +2*(col&1).
    const int fkt = col >> 4;
    const int fr  = col & 15;
    const uint32_t fragOff0 = (uint32_t)((((fkt >> 1) * 32 + ne0 * 4 + ((fr & 7) >> 1)) * 16) +
                                         (fkt & 1) * 8 + ((fr & 8) ? 4 : 0) + (col & 1) * 2);
    const uint32_t fragOff1 = fragOff0 + 64;   // ne1 = ne0+1 -> +4 slots
    const uint32_t base0 = (uint32_t)__cvta_generic_to_shared(&bbuf[0][0][0]);
    const uint32_t base1 = (uint32_t)__cvta_generic_to_shared(&bbuf[1][0][0]);

    // --- A-fragments (gate-interleaved tiles), loaded once ---
    uint32_t afrag[2][8][4];
#pragma unroll
    for (int mt = 0; mt < 2; mt++) {
        const float* wlo = Whh + (size_t)((2 * mt)     * 128 + warp * 8 + r0) * HDIM;
        const float* whi = Whh + (size_t)((2 * mt + 1) * 128 + warp * 8 + r0) * HDIM;
#pragma unroll
        for (int kt = 0; kt < 8; kt++) {
            const int k = kt * 16 + q * 2;
            float2 w00 = *reinterpret_cast<const float2*>(wlo + k);
            float2 w01 = *reinterpret_cast<const float2*>(wlo + k + 8);
            float2 w10 = *reinterpret_cast<const float2*>(whi + k);
            float2 w11 = *reinterpret_cast<const float2*>(whi + k + 8);
            afrag[mt][kt][0] = f2h2(w00.x, w00.y);
            afrag[mt][kt][1] = f2h2(w10.x, w10.y);
            afrag[mt][kt][2] = f2h2(w01.x, w01.y);
            afrag[mt][kt][3] = f2h2(w11.x, w11.y);
        }
    }

    // --- mask table (8 rows) ---
    for (int idx = tid; idx < LSEQ * 8; idx += 512) {
        const int t = idx >> 3, r = idx & 7;
        msk[t][r] = 1.0f - (float)is_init[(size_t)t * NBATCH + n0 + r];
    }
    __syncthreads();

    // --- first reset in [256,512) per row (mask==0 there) ---
    if (tid < 8) {
        int p = 512;
        for (int t = 256; t < 512; t++)
            if (msk[t][tid] == 0.0f) { p = t; break; }
        pp[tid] = p;
    }
    __syncthreads();
    int pmax = 0;
#pragma unroll
    for (int r = 0; r < 8; r++) pmax = max(pmax, pp[r]);

    const int tBeg = chunk ? 256 : 0;
    const int tEnd = chunk ? 512 : pmax;
    const int p0 = pp[ne0], p1 = pp[ne1];

    // --- init state + publish h(tBeg) into fragment slots (buf 0; tBeg even) ---
    float creg0, creg1;
    if (chunk == 0) {
        const float m00 = msk[0][ne0], m01 = msk[0][ne1];
        creg0 = hc[(size_t)ng0 * 256 + 128 + col] * m00;
        creg1 = hc[(size_t)ng1 * 256 + 128 + col] * m01;
        const __half h0 = __float2half(hc[(size_t)ng0 * 256 + col] * m00);
        const __half h1 = __float2half(hc[(size_t)ng1 * 256 + col] * m01);
        asm volatile("st.shared.u16 [%0], %1;"
                     :: "r"(base0 + fragOff0), "h"(*reinterpret_cast<const uint16_t*>(&h0)));
        asm volatile("st.shared.u16 [%0], %1;"
                     :: "r"(base0 + fragOff1), "h"(*reinterpret_cast<const uint16_t*>(&h1)));
    } else {
        creg0 = 0.0f; creg1 = 0.0f;
        asm volatile("st.shared.u16 [%0], %1;" :: "r"(base0 + fragOff0), "h"((uint16_t)0));
        asm volatile("st.shared.u16 [%0], %1;" :: "r"(base0 + fragOff1), "h"((uint16_t)0));
    }
    __syncthreads();   // h(tBeg) visible

    const uint2* xgp = reinterpret_cast<const uint2*>(g_XgH);
    uint2 x0 = __ldg(&xgp[((size_t)tBeg * NBATCH + ng0) * 128 + col]);
    uint2 x1 = __ldg(&xgp[((size_t)tBeg * NBATCH + ng1) * 128 + col]);

    // B-fragment read base: 4 x LDS.128 at slot = lane (all 32 distinct)
    const uint32_t bRead0 = base0 + (uint32_t)lane * 16;
    const uint32_t bRead1 = base1 + (uint32_t)lane * 16;

    const size_t OUT_HC = (size_t)LSEQ * NBATCH * HDIM;

#pragma unroll 1
    for (int t = tBeg; t < tEnd; t++) {
        // state-independent prefetches (t+1; array padded)
        uint2 xn0 = __ldg(&xgp[((size_t)(t + 1) * NBATCH + ng0) * 128 + col]);
        uint2 xn1 = __ldg(&xgp[((size_t)(t + 1) * NBATCH + ng1) * 128 + col]);
        const float mn0 = (t < LSEQ - 1) ? msk[t + 1][ne0] : 1.0f;
        const float mn1 = (t < LSEQ - 1) ? msk[t + 1][ne1] : 1.0f;

        const int sbase = 1 + 2 * (t & 1);
        const uint32_t brd = (t & 1) ? bRead1 : bRead0;

        float acc[2][4], accB[2][4];
#pragma unroll
        for (int mt = 0; mt < 2; mt++)
#pragma unroll
            for (int p = 0; p < 4; p++) { acc[mt][p] = 0.0f; accB[mt][p] = 0.0f; }

        // --- chunk 0 of K: cols 0-63 (published by warps 0-7) ---
        if (t != tBeg) nbar_sync768(sbase);
#pragma unroll
        for (int kt2 = 0; kt2 < 2; kt2++) {
            uint32_t b0, b1, c0_, c1_;
            asm volatile("ld.shared.v4.u32 {%0,%1,%2,%3}, [%4];"
                         : "=r"(b0), "=r"(b1), "=r"(c0_), "=r"(c1_)
                         : "r"(brd + kt2 * 512));
#pragma unroll
            for (int mt = 0; mt < 2; mt++) {
                mma16816(acc[mt],  afrag[mt][2*kt2][0],   afrag[mt][2*kt2][1],
                                   afrag[mt][2*kt2][2],   afrag[mt][2*kt2][3],   b0, b1);
                mma16816(accB[mt], afrag[mt][2*kt2+1][0], afrag[mt][2*kt2+1][1],
                                   afrag[mt][2*kt2+1][2], afrag[mt][2*kt2+1][3], c0_, c1_);
            }
        }
        // --- chunk 1 of K: cols 64-127 (published by warps 8-15) ---
        if (t != tBeg) nbar_sync768(sbase + 1);
#pragma unroll
        for (int kt2 = 2; kt2 < 4; kt2++) {
            uint32_t b0, b1, c0_, c1_;
            asm volatile("ld.shared.v4.u32 {%0,%1,%2,%3}, [%4];"
                         : "=r"(b0), "=r"(b1), "=r"(c0_), "=r"(c1_)
                         : "r"(brd + kt2 * 512));
#pragma unroll
            for (int mt = 0; mt < 2; mt++) {
                mma16816(acc[mt],  afrag[mt][2*kt2][0],   afrag[mt][2*kt2][1],
                                   afrag[mt][2*kt2][2],   afrag[mt][2*kt2][3],   b0, b1);
                mma16816(accB[mt], afrag[mt][2*kt2+1][0], afrag[mt][2*kt2+1][1],
                                   afrag[mt][2*kt2+1][2], afrag[mt][2*kt2+1][3], c0_, c1_);
            }
        }

        // gates: element e0 (n=2q) and e1 (n=2q+1), all in-register
        const float gi0 = acc[0][0] + accB[0][0], gi1 = acc[0][1] + accB[0][1];
        const float gf0 = acc[0][2] + accB[0][2], gf1 = acc[0][3] + accB[0][3];
        const float gg0 = acc[1][0] + accB[1][0], gg1 = acc[1][1] + accB[1][1];
        const float go0 = acc[1][2] + accB[1][2], go1 = acc[1][3] + accB[1][3];

        const float2 a01 = __half22float2(*reinterpret_cast<__half2*>(&x0.x));
        const float2 a23 = __half22float2(*reinterpret_cast<__half2*>(&x0.y));
        const float2 b01 = __half22float2(*reinterpret_cast<__half2*>(&x1.x));
        const float2 b23 = __half22float2(*reinterpret_cast<__half2*>(&x1.y));

        const float i0 = sigg(gi0 + a01.x);
        const float f0 = sigg(gf0 + a01.y);
        const float g0 = tanhg(gg0 + a23.x);
        const float o0 = sigg(go0 + a23.y);
        const float cn0 = __fmaf_rn(f0, creg0, i0 * g0);
        const float hv0 = o0 * tanhg(cn0);

        const float i1 = sigg(gi1 + b01.x);
        const float f1 = sigg(gf1 + b01.y);
        const float g1 = tanhg(gg1 + b23.x);
        const float o1 = sigg(go1 + b23.y);
        const float cn1 = __fmaf_rn(f1, creg1, i1 * g1);
        const float hv1 = o1 * tanhg(cn1);

        creg0 = cn0 * mn0;
        creg1 = cn1 * mn1;

        // publish h(t+1) into fragment slots, then arrive (release)
        {
            const __half hm0 = __float2half(hv0 * mn0);
            const __half hm1 = __float2half(hv1 * mn1);
            const uint32_t dst = ((t + 1) & 1) ? base1 : base0;
            asm volatile("st.shared.u16 [%0], %1;"
                         :: "r"(dst + fragOff0), "h"(*reinterpret_cast<const uint16_t*>(&hm0)));
            asm volatile("st.shared.u16 [%0], %1;"
                         :: "r"(dst + fragOff1), "h"(*reinterpret_cast<const uint16_t*>(&hm1)));
        }
        nbar_arrive768(1 + 2 * ((t + 1) & 1) + myHalf);

        // stores after arrive (overlap other warps' MMA). chunk1 suppresses
        // garbage prefix (t < p_n); overlap region writes are bitwise equal.
        if (chunk == 0 || t >= p0)
            out[((size_t)t * NBATCH + ng0) * HDIM + col] = hv0;
        if (chunk == 0 || t >= p1)
            out[((size_t)t * NBATCH + ng1) * HDIM + col] = hv1;

        if (t == LSEQ - 1) {
            // final hc ownership: chunk1 iff p_n<512, chunk0 iff p_n==512
            const bool own0 = chunk ? (p0 < 512) : (p0 == 512);
            const bool own1 = chunk ? (p1 < 512) : (p1 == 512);
            if (own0) {
                out[OUT_HC + (size_t)ng0 * 256 + col]       = hv0;
                out[OUT_HC + (size_t)ng0 * 256 + 128 + col] = cn0;
            }
            if (own1) {
                out[OUT_HC + (size_t)ng1 * 256 + col]       = hv1;
                out[OUT_HC + (size_t)ng1 * 256 + 128 + col] = cn1;
            }
        }
        x0 = xn0; x1 = xn1;
    }
}

// ---------------------------------------------------------------------------
extern "C" void kernel_launch(void* const* d_in, const int* in_sizes, int n_in,
                              void* d_out, int out_size)
{
    const float* input   = (const float*)d_in[0];  // [L,N,I] fp32
    const float* hc      = (const float*)d_in[1];  // [N,2H]  fp32
    const int*   is_init = (const int*)  d_in[2];  // [L,N]   int32
    const float* Wih     = (const float*)d_in[3];  // [4H,I]
    const float* Whh     = (const float*)d_in[4];  // [4H,H]
    const float* bih     = (const float*)d_in[5];  // [4H]
    const float* bhh     = (const float*)d_in[6];  // [4H]
    float* out = (float*)d_out;                    // [L,N,H] then [N,2H]

    pregemm_kernel<<<(LSEQ * NBATCH / 256) * 2, 256>>>(input, Wih, bih, bhh);
    lstm_rec_kernel<<<(NBATCH / 8) * 2, 512>>>(hc, is_init, Whh, out);
}